// round 1
// baseline (speedup 1.0000x reference)
#include <cuda_runtime.h>
#include <math.h>

#define N_COMBOS   64
#define N_STRUCTS  512
#define HID        1024
#define BATCH      2048
#define NITERS     60
#define POW_ITERS  30

#define MAX_NNZ_G  32768     // worst case (dense)
#define MAX_NNZ_S  6144      // >> 60 sigma above expected ~3100

// ---------------- device scratch (no allocations allowed) ----------------
__device__ float g_A1[BATCH * HID];
__device__ float g_A2[BATCH * HID];
__device__ float g_Z [BATCH * N_STRUCTS];
__device__ float g_tau;

__device__ int            g_row_ptr[N_COMBOS + 1];
__device__ unsigned short g_row_idx[MAX_NNZ_G];
__device__ int            g_col_ptr[N_STRUCTS + 1];
__device__ unsigned char  g_col_idx[MAX_NNZ_G];

// ---------------- prep: build CSR (rows) + CSC (cols) of S ----------------
__global__ __launch_bounds__(512) void prep_kernel(const float* __restrict__ S) {
    __shared__ int cnt[N_STRUCTS];
    int tid = threadIdx.x;

    // rows (64)
    if (tid < N_COMBOS) {
        int c = 0;
        for (int j = 0; j < N_STRUCTS; j++) if (S[tid * N_STRUCTS + j] != 0.f) c++;
        cnt[tid] = c;
    }
    __syncthreads();
    if (tid == 0) {
        int acc = 0;
        for (int i = 0; i < N_COMBOS; i++) { g_row_ptr[i] = acc; acc += cnt[i]; }
        g_row_ptr[N_COMBOS] = acc;
    }
    __syncthreads();
    if (tid < N_COMBOS) {
        int p = g_row_ptr[tid];
        for (int j = 0; j < N_STRUCTS; j++)
            if (S[tid * N_STRUCTS + j] != 0.f) g_row_idx[p++] = (unsigned short)j;
    }
    __syncthreads();

    // cols (512)
    {
        int c = 0;
        for (int i = 0; i < N_COMBOS; i++) if (S[i * N_STRUCTS + tid] != 0.f) c++;
        cnt[tid] = c;
    }
    __syncthreads();
    if (tid == 0) {
        int acc = 0;
        for (int j = 0; j < N_STRUCTS; j++) { g_col_ptr[j] = acc; acc += cnt[j]; }
        g_col_ptr[N_STRUCTS] = acc;
    }
    __syncthreads();
    {
        int p = g_col_ptr[tid];
        for (int i = 0; i < N_COMBOS; i++)
            if (S[i * N_STRUCTS + tid] != 0.f) g_col_idx[p++] = (unsigned char)i;
    }
}

// ---------------- power iteration: tau = 0.9 / ||K||_2 ----------------
__global__ __launch_bounds__(512) void power_kernel() {
    __shared__ float v[N_STRUCTS];
    __shared__ float t[N_COMBOS];
    __shared__ float red[16];
    int tid = threadIdx.x;

    v[tid] = 1.0f / sqrtf((float)N_STRUCTS);
    __syncthreads();

    for (int it = 0; it < POW_ITERS; it++) {
        if (tid < N_COMBOS) {
            float s = 0.f;
            int pe = g_row_ptr[tid + 1];
            for (int p = g_row_ptr[tid]; p < pe; p++) s += v[g_row_idx[p]];
            t[tid] = s;
        }
        __syncthreads();
        float w;
        {
            float s = 0.f;
            int pe = g_col_ptr[tid + 1];
            for (int p = g_col_ptr[tid]; p < pe; p++) s += t[g_col_idx[p]];
            w = s + v[tid];
        }
        float sq = w * w;
        #pragma unroll
        for (int o = 16; o; o >>= 1) sq += __shfl_xor_sync(0xffffffffu, sq, o);
        if ((tid & 31) == 0) red[tid >> 5] = sq;
        __syncthreads();
        float tot = 0.f;
        #pragma unroll
        for (int k = 0; k < 16; k++) tot += red[k];
        float nrm = sqrtf(tot);
        v[tid] = w / nrm;
        __syncthreads();
    }

    // L = sqrt( v . (S^T S v + v) )
    if (tid < N_COMBOS) {
        float s = 0.f;
        int pe = g_row_ptr[tid + 1];
        for (int p = g_row_ptr[tid]; p < pe; p++) s += v[g_row_idx[p]];
        t[tid] = s;
    }
    __syncthreads();
    float w;
    {
        float s = 0.f;
        int pe = g_col_ptr[tid + 1];
        for (int p = g_col_ptr[tid]; p < pe; p++) s += t[g_col_idx[p]];
        w = s + v[tid];
    }
    float dq = v[tid] * w;
    #pragma unroll
    for (int o = 16; o; o >>= 1) dq += __shfl_xor_sync(0xffffffffu, dq, o);
    if ((tid & 31) == 0) red[tid >> 5] = dq;
    __syncthreads();
    if (tid == 0) {
        float tot = 0.f;
        #pragma unroll
        for (int k = 0; k < 16; k++) tot += red[k];
        float L = sqrtf(tot);
        g_tau = 0.9f / L;
    }
}

// ---------------- GEMM + bias + relu  (C = relu(A@B + bias)) ----------------
// BM=128, BN=64, BK=16, 256 threads, TM=8, TN=4
template<int BM, int BN, int BK, int TM, int TN>
__global__ __launch_bounds__(256) void gemm_bias_relu(
    const float* __restrict__ A, const float* __restrict__ B,
    const float* __restrict__ bias, float* __restrict__ C,
    int M, int N, int K)
{
    __shared__ __align__(16) float As[BK][BM];
    __shared__ __align__(16) float Bs[BK][BN];

    const int tid = threadIdx.x;
    const int bm = blockIdx.y * BM;
    const int bn = blockIdx.x * BN;

    const int TNX = BN / TN;              // threads along N (16)
    const int tx = tid % TNX;
    const int ty = tid / TNX;             // 0..15

    // A tile load: BM x BK floats, float4 along K
    const int a_r = tid / (BK / 4);       // 0..63
    const int a_c = (tid % (BK / 4)) * 4; // 0,4,8,12
    // B tile load: BK x BN floats, float4 along N
    const int b_r = tid / (BN / 4);       // 0..15
    const int b_c = (tid % (BN / 4)) * 4;

    float acc[TM][TN];
    #pragma unroll
    for (int i = 0; i < TM; i++)
        #pragma unroll
        for (int j = 0; j < TN; j++) acc[i][j] = 0.f;

    for (int k0 = 0; k0 < K; k0 += BK) {
        #pragma unroll
        for (int rr = 0; rr < BM; rr += 64) {
            float4 av = *(const float4*)&A[(size_t)(bm + a_r + rr) * K + k0 + a_c];
            As[a_c + 0][a_r + rr] = av.x;
            As[a_c + 1][a_r + rr] = av.y;
            As[a_c + 2][a_r + rr] = av.z;
            As[a_c + 3][a_r + rr] = av.w;
        }
        {
            float4 bv = *(const float4*)&B[(size_t)(k0 + b_r) * N + bn + b_c];
            *(float4*)&Bs[b_r][b_c] = bv;
        }
        __syncthreads();

        #pragma unroll
        for (int k = 0; k < BK; k++) {
            float a[TM], b[TN];
            const float4* a4 = (const float4*)&As[k][ty * TM];
            const float4* b4 = (const float4*)&Bs[k][tx * TN];
            float4 av0 = a4[0], av1 = a4[1];
            a[0]=av0.x; a[1]=av0.y; a[2]=av0.z; a[3]=av0.w;
            a[4]=av1.x; a[5]=av1.y; a[6]=av1.z; a[7]=av1.w;
            float4 bv0 = b4[0];
            b[0]=bv0.x; b[1]=bv0.y; b[2]=bv0.z; b[3]=bv0.w;
            #pragma unroll
            for (int i = 0; i < TM; i++)
                #pragma unroll
                for (int j = 0; j < TN; j++)
                    acc[i][j] = fmaf(a[i], b[j], acc[i][j]);
        }
        __syncthreads();
    }

    #pragma unroll
    for (int j = 0; j < TN; j++) {
        float bb = bias[bn + tx * TN + j];
        #pragma unroll
        for (int i = 0; i < TM; i++) {
            float r = acc[i][j] + bb;
            C[(size_t)(bm + ty * TM + i) * N + bn + tx * TN + j] = r > 0.f ? r : 0.f;
        }
    }
}

// ---------------- PDHG: one block per batch row ----------------
__global__ __launch_bounds__(128) void pdhg_kernel(
    const float* __restrict__ Zg, const float* __restrict__ Xg,
    float* __restrict__ out)
{
    constexpr int T = 128;
    constexpr int Q = N_STRUCTS / T;  // 4

    __shared__ float xbar[N_STRUCTS];
    __shared__ float y1s[N_COMBOS];
    __shared__ float Brow[N_COMBOS];
    __shared__ float red[4];
    __shared__ int            s_row_ptr[N_COMBOS + 1];
    __shared__ unsigned short s_row_idx[MAX_NNZ_S];
    __shared__ unsigned short s_col_ptr[N_STRUCTS + 1];
    __shared__ unsigned char  s_col_idx[MAX_NNZ_S];

    const int tid = threadIdx.x;
    const int row = blockIdx.x;
    const float tau = g_tau;
    const float sigma = tau;

    const int nnz = g_row_ptr[N_COMBOS];
    for (int p = tid; p <= N_COMBOS; p += T) s_row_ptr[p] = g_row_ptr[p];
    for (int p = tid; p < nnz && p < MAX_NNZ_S; p += T) s_row_idx[p] = g_row_idx[p];
    for (int p = tid; p <= N_STRUCTS; p += T) s_col_ptr[p] = (unsigned short)g_col_ptr[p];
    for (int p = tid; p < nnz && p < MAX_NNZ_S; p += T) s_col_idx[p] = g_col_idx[p];
    if (tid < N_COMBOS) {
        Brow[tid] = Xg[row * N_COMBOS + tid];
        y1s[tid] = 0.f;
    }

    float Zr[Q], xr[Q], y2r[Q], xbr[Q], dq[Q];
    #pragma unroll
    for (int q = 0; q < Q; q++) {
        int j = tid + q * T;
        Zr[q] = Zg[(size_t)row * N_STRUCTS + j];
        xr[q] = 0.f; y2r[q] = 0.f; xbr[q] = 0.f;
        xbar[j] = 0.f;
    }
    __syncthreads();

    for (int it = 0; it < NITERS; it++) {
        // y2 update (local, uses xbar from prev iter held in regs)
        #pragma unroll
        for (int q = 0; q < Q; q++)
            y2r[q] = fmaxf(fmaf(-sigma, xbr[q], y2r[q]), 0.f);

        // y1 update (threads 0..63): t1[i] = sum_{j in row_i} xbar[j]
        if (tid < N_COMBOS) {
            float s = 0.f;
            int pe = s_row_ptr[tid + 1];
            for (int p = s_row_ptr[tid]; p < pe; p++) s += xbar[s_row_idx[p]];
            y1s[tid] = fmaxf(fmaf(sigma, s - Brow[tid], y1s[tid]), 0.f);
        }
        __syncthreads();

        // g = S^T y1 - y2 ; prox prep
        float sumsq = 0.f;
        #pragma unroll
        for (int q = 0; q < Q; q++) {
            int j = tid + q * T;
            float g = 0.f;
            int pe = s_col_ptr[j + 1];
            for (int p = s_col_ptr[j]; p < pe; p++) g += y1s[s_col_idx[p]];
            g -= y2r[q];
            float v = fmaf(-tau, g, xr[q]);
            float d = v + tau - Zr[q];
            dq[q] = d;
            sumsq = fmaf(d, d, sumsq);
        }
        #pragma unroll
        for (int o = 16; o; o >>= 1) sumsq += __shfl_xor_sync(0xffffffffu, sumsq, o);
        if ((tid & 31) == 0) red[tid >> 5] = sumsq;
        __syncthreads();

        float nrm = sqrtf(red[0] + red[1] + red[2] + red[3]);
        float scale = fmaxf(1.f - tau / fmaxf(nrm, 1e-12f), 0.f);

        #pragma unroll
        for (int q = 0; q < Q; q++) {
            int j = tid + q * T;
            float xn = fmaf(scale, dq[q], Zr[q]);
            float xb = 2.f * xn - xr[q];
            xr[q] = xn;
            xbr[q] = xb;
            xbar[j] = xb;
        }
        __syncthreads();
    }

    #pragma unroll
    for (int q = 0; q < Q; q++)
        out[(size_t)row * N_STRUCTS + tid + q * T] = xr[q];
}

// ---------------- launch ----------------
extern "C" void kernel_launch(void* const* d_in, const int* in_sizes, int n_in,
                              void* d_out, int out_size) {
    const float* X  = (const float*)d_in[0];   // [2048,4,16] -> [2048,64]
    const float* W1 = (const float*)d_in[1];   // [64,1024]
    const float* b1 = (const float*)d_in[2];
    const float* W2 = (const float*)d_in[3];   // [1024,1024]
    const float* b2 = (const float*)d_in[4];
    const float* W3 = (const float*)d_in[5];   // [1024,512]
    const float* b3 = (const float*)d_in[6];
    const float* S  = (const float*)d_in[7];   // [64,512]
    float* out = (float*)d_out;                // [2048,512]

    float *A1, *A2, *Z;
    cudaGetSymbolAddress((void**)&A1, g_A1);
    cudaGetSymbolAddress((void**)&A2, g_A2);
    cudaGetSymbolAddress((void**)&Z,  g_Z);

    prep_kernel<<<1, 512>>>(S);
    power_kernel<<<1, 512>>>();

    // L1: [2048,64] @ [64,1024]
    gemm_bias_relu<128, 64, 16, 8, 4><<<dim3(HID / 64, BATCH / 128), 256>>>(
        X, W1, b1, A1, BATCH, HID, N_COMBOS);
    // L2: [2048,1024] @ [1024,1024]
    gemm_bias_relu<128, 64, 16, 8, 4><<<dim3(HID / 64, BATCH / 128), 256>>>(
        A1, W2, b2, A2, BATCH, HID, HID);
    // L3: [2048,1024] @ [1024,512]
    gemm_bias_relu<128, 64, 16, 8, 4><<<dim3(N_STRUCTS / 64, BATCH / 128), 256>>>(
        A2, W3, b3, Z, BATCH, N_STRUCTS, HID);

    pdhg_kernel<<<BATCH, 128>>>(Z, X, out);
}

// round 2
// speedup vs baseline: 1.7457x; 1.7457x over previous
#include <cuda_runtime.h>
#include <math.h>

#define N_COMBOS   64
#define N_STRUCTS  512
#define HID        1024
#define BATCH      2048
#define NITERS     60
#define POW_ITERS  30

#define MAX_NNZ_G  32768
#define MAX_LR     96        // padded ELL steps for row pairs (max row deg ~68 expected)
#define COLCAP     8192      // padded CSC bytes (expected ~4096)
#define ROWS_PER_BLK 8

// ---------------- device scratch ----------------
__device__ float g_A1[BATCH * HID];
__device__ float g_A2[BATCH * HID];
__device__ float g_Z [BATCH * N_STRUCTS];
__device__ float g_tau;

__device__ int            g_row_ptr[N_COMBOS + 1];
__device__ unsigned short g_row_idx[MAX_NNZ_G];
__device__ int            g_col_ptr[N_STRUCTS + 1];
__device__ unsigned char  g_col_idx[MAX_NNZ_G];

// packed formats for PDHG
__device__ unsigned int   g_ellr[MAX_LR * 32];   // [p][lane]: idx(row=lane) | idx(row=lane+32)<<16 ; sentinel 512
__device__ int            g_len_ellr;
__device__ unsigned short g_cp4[N_STRUCTS + 1];  // padded (mult of 4) CSC offsets
__device__ unsigned char  g_ci4[COLCAP];         // padded CSC col indices; sentinel 64

// ---------------- prep: CSR + CSC + packed ELL/CSC4 ----------------
__global__ __launch_bounds__(512) void prep_kernel(const float* __restrict__ S) {
    __shared__ int cnt[N_STRUCTS];
    int tid = threadIdx.x;

    // rows (64)
    if (tid < N_COMBOS) {
        int c = 0;
        for (int j = 0; j < N_STRUCTS; j++) if (S[tid * N_STRUCTS + j] != 0.f) c++;
        cnt[tid] = c;
    }
    __syncthreads();
    if (tid == 0) {
        int acc = 0;
        for (int i = 0; i < N_COMBOS; i++) { g_row_ptr[i] = acc; acc += cnt[i]; }
        g_row_ptr[N_COMBOS] = acc;
    }
    __syncthreads();
    if (tid < N_COMBOS) {
        int p = g_row_ptr[tid];
        for (int j = 0; j < N_STRUCTS; j++)
            if (S[tid * N_STRUCTS + j] != 0.f) g_row_idx[p++] = (unsigned short)j;
    }
    __syncthreads();

    // cols (512)
    {
        int c = 0;
        for (int i = 0; i < N_COMBOS; i++) if (S[i * N_STRUCTS + tid] != 0.f) c++;
        cnt[tid] = c;
    }
    __syncthreads();
    if (tid == 0) {
        int acc = 0;
        for (int j = 0; j < N_STRUCTS; j++) { g_col_ptr[j] = acc; acc += cnt[j]; }
        g_col_ptr[N_STRUCTS] = acc;
    }
    __syncthreads();
    {
        int p = g_col_ptr[tid];
        for (int i = 0; i < N_COMBOS; i++)
            if (S[i * N_STRUCTS + tid] != 0.f) g_col_idx[p++] = (unsigned char)i;
    }
    __syncthreads();

    // packed row-pair ELL (lanes 0..31)
    if (tid < 32) {
        int ra = g_row_ptr[tid],      la = g_row_ptr[tid + 1]  - ra;
        int rb = g_row_ptr[tid + 32], lb = g_row_ptr[tid + 33] - rb;
        int L = la > lb ? la : lb;
        if (L > MAX_LR) L = MAX_LR;
        for (int p = 0; p < MAX_LR; p++) {
            unsigned a = (p < la) ? g_row_idx[ra + p] : 512u;
            unsigned b = (p < lb) ? g_row_idx[rb + p] : 512u;
            g_ellr[p * 32 + tid] = a | (b << 16);
        }
        #pragma unroll
        for (int o = 16; o; o >>= 1) { int v = __shfl_xor_sync(0xffffffffu, L, o); L = v > L ? v : L; }
        if (tid == 0) g_len_ellr = L;
    }
    // padded CSC offsets (thread 0, small)
    if (tid == 0) {
        int acc = 0;
        for (int j = 0; j < N_STRUCTS; j++) {
            g_cp4[j] = (unsigned short)acc;
            int l = g_col_ptr[j + 1] - g_col_ptr[j];
            acc += (l + 3) & ~3;
        }
        g_cp4[N_STRUCTS] = (unsigned short)acc;
    }
    __syncthreads();
    {
        int j = tid;
        int o = g_cp4[j];
        int base = g_col_ptr[j];
        int l = g_col_ptr[j + 1] - base;
        int pl = (l + 3) & ~3;
        for (int p = 0; p < pl && (o + p) < COLCAP; p++)
            g_ci4[o + p] = (p < l) ? g_col_idx[base + p] : (unsigned char)64;
    }
}

// ---------------- power iteration: tau = 0.9 / ||K||_2 ----------------
__global__ __launch_bounds__(512) void power_kernel() {
    __shared__ float v[N_STRUCTS];
    __shared__ float t[N_COMBOS];
    __shared__ float red[16];
    int tid = threadIdx.x;

    v[tid] = 1.0f / sqrtf((float)N_STRUCTS);
    __syncthreads();

    for (int it = 0; it < POW_ITERS; it++) {
        if (tid < N_COMBOS) {
            float s = 0.f;
            int pe = g_row_ptr[tid + 1];
            for (int p = g_row_ptr[tid]; p < pe; p++) s += v[g_row_idx[p]];
            t[tid] = s;
        }
        __syncthreads();
        float w;
        {
            float s = 0.f;
            int pe = g_col_ptr[tid + 1];
            for (int p = g_col_ptr[tid]; p < pe; p++) s += t[g_col_idx[p]];
            w = s + v[tid];
        }
        float sq = w * w;
        #pragma unroll
        for (int o = 16; o; o >>= 1) sq += __shfl_xor_sync(0xffffffffu, sq, o);
        if ((tid & 31) == 0) red[tid >> 5] = sq;
        __syncthreads();
        float tot = 0.f;
        #pragma unroll
        for (int k = 0; k < 16; k++) tot += red[k];
        float nrm = sqrtf(tot);
        v[tid] = w / nrm;
        __syncthreads();
    }

    if (tid < N_COMBOS) {
        float s = 0.f;
        int pe = g_row_ptr[tid + 1];
        for (int p = g_row_ptr[tid]; p < pe; p++) s += v[g_row_idx[p]];
        t[tid] = s;
    }
    __syncthreads();
    float w;
    {
        float s = 0.f;
        int pe = g_col_ptr[tid + 1];
        for (int p = g_col_ptr[tid]; p < pe; p++) s += t[g_col_idx[p]];
        w = s + v[tid];
    }
    float dq = v[tid] * w;
    #pragma unroll
    for (int o = 16; o; o >>= 1) dq += __shfl_xor_sync(0xffffffffu, dq, o);
    if ((tid & 31) == 0) red[tid >> 5] = dq;
    __syncthreads();
    if (tid == 0) {
        float tot = 0.f;
        #pragma unroll
        for (int k = 0; k < 16; k++) tot += red[k];
        g_tau = 0.9f / sqrtf(tot);
    }
}

// ---------------- GEMM + bias + relu  (C = relu(A@B + bias)) ----------------
// BM=64, BN=64, BK=16, 256 threads, TM=4, TN=4 -> more blocks, better occupancy
template<int BM, int BN, int BK, int TM, int TN>
__global__ __launch_bounds__(256) void gemm_bias_relu(
    const float* __restrict__ A, const float* __restrict__ B,
    const float* __restrict__ bias, float* __restrict__ C,
    int M, int N, int K)
{
    __shared__ __align__(16) float As[BK][BM];
    __shared__ __align__(16) float Bs[BK][BN];

    const int tid = threadIdx.x;
    const int bm = blockIdx.y * BM;
    const int bn = blockIdx.x * BN;

    const int TNX = BN / TN;              // 16
    const int tx = tid % TNX;
    const int ty = tid / TNX;             // 0..15

    const int a_r = tid >> 2;             // 0..63
    const int a_c = (tid & 3) * 4;        // 0,4,8,12
    const int b_r = tid >> 4;             // 0..15
    const int b_c = (tid & 15) * 4;

    float acc[TM][TN];
    #pragma unroll
    for (int i = 0; i < TM; i++)
        #pragma unroll
        for (int j = 0; j < TN; j++) acc[i][j] = 0.f;

    for (int k0 = 0; k0 < K; k0 += BK) {
        {
            float4 av = *(const float4*)&A[(size_t)(bm + a_r) * K + k0 + a_c];
            As[a_c + 0][a_r] = av.x;
            As[a_c + 1][a_r] = av.y;
            As[a_c + 2][a_r] = av.z;
            As[a_c + 3][a_r] = av.w;
        }
        {
            float4 bv = *(const float4*)&B[(size_t)(k0 + b_r) * N + bn + b_c];
            *(float4*)&Bs[b_r][b_c] = bv;
        }
        __syncthreads();

        #pragma unroll
        for (int k = 0; k < BK; k++) {
            float4 av = *(const float4*)&As[k][ty * TM];
            float4 bv = *(const float4*)&Bs[k][tx * TN];
            float a[4] = {av.x, av.y, av.z, av.w};
            float b[4] = {bv.x, bv.y, bv.z, bv.w};
            #pragma unroll
            for (int i = 0; i < TM; i++)
                #pragma unroll
                for (int j = 0; j < TN; j++)
                    acc[i][j] = fmaf(a[i], b[j], acc[i][j]);
        }
        __syncthreads();
    }

    #pragma unroll
    for (int j = 0; j < TN; j++) {
        float bb = bias[bn + tx * TN + j];
        #pragma unroll
        for (int i = 0; i < TM; i++) {
            float r = acc[i][j] + bb;
            C[(size_t)(bm + ty * TM + i) * N + bn + tx * TN + j] = r > 0.f ? r : 0.f;
        }
    }
}

// ---------------- PDHG: one WARP per batch row, 8 warps per block ----------------
__global__ __launch_bounds__(256, 2) void pdhg_warp_kernel(
    const float* __restrict__ Zg, const float* __restrict__ Xg,
    float* __restrict__ out)
{
    constexpr int XB = 516;  // 512 + sentinel slot(s)
    __shared__ unsigned int   s_ellr[MAX_LR * 32];           // 12 KB
    __shared__ unsigned short s_cp4[N_STRUCTS + 2];          // ~1 KB
    __shared__ unsigned char  s_ci4[COLCAP];                 // 8 KB
    __shared__ float          s_xbar[ROWS_PER_BLK][XB];      // 16.1 KB
    __shared__ float          s_y1[ROWS_PER_BLK][68];        // 2.1 KB

    const int tid = threadIdx.x;
    const int w   = tid >> 5;
    const int l   = tid & 31;
    const int row = blockIdx.x * ROWS_PER_BLK + w;
    const float tau = g_tau;
    const float sigma = tau;
    const int LEN = g_len_ellr;

    // cooperative copies of shared structure
    for (int p = tid; p < LEN * 32; p += 256) s_ellr[p] = g_ellr[p];
    for (int p = tid; p <= N_STRUCTS; p += 256) s_cp4[p] = g_cp4[p];
    {
        int tot = (g_cp4[N_STRUCTS] + 3) & ~3;
        for (int p = tid * 4; p < tot; p += 1024)
            *(unsigned int*)&s_ci4[p] = *(const unsigned int*)&g_ci4[p];
    }

    // per-warp state
    float* sx  = s_xbar[w];
    float* sy1 = s_y1[w];

    const float B0 = Xg[row * N_COMBOS + l];
    const float B1 = Xg[row * N_COMBOS + l + 32];
    float yy0 = 0.f, yy1 = 0.f;

    float Zr[16], xr[16], y2[16], xb[16], dq[16];
    #pragma unroll
    for (int q = 0; q < 16; q++) {
        int j = q * 32 + l;
        Zr[q] = Zg[(size_t)row * N_STRUCTS + j];
        xr[q] = 0.f; y2[q] = 0.f; xb[q] = 0.f;
        sx[j] = 0.f;
    }
    if (l < XB - 512) sx[512 + l] = 0.f;       // sentinel
    if (l < 4) sy1[64 + l] = 0.f;              // sentinel
    __syncthreads();                            // structure copies ready

    for (int it = 0; it < NITERS; it++) {
        // ---- y1 = max(y1 + sigma*(S xbar - B), 0): row-pair gather ----
        float s0 = 0.f, s1 = 0.f;
        for (int p = 0; p < LEN; p++) {
            unsigned u = s_ellr[p * 32 + l];
            s0 += sx[u & 0xffffu];
            s1 += sx[u >> 16];
        }
        yy0 = fmaxf(fmaf(sigma, s0 - B0, yy0), 0.f);
        yy1 = fmaxf(fmaf(sigma, s1 - B1, yy1), 0.f);
        sy1[l] = yy0;
        sy1[l + 32] = yy1;

        // ---- y2 = max(y2 - sigma*xbar, 0) (xbar held in regs) ----
        #pragma unroll
        for (int q = 0; q < 16; q++)
            y2[q] = fmaxf(fmaf(-sigma, xb[q], y2[q]), 0.f);
        __syncwarp();

        // ---- g = S^T y1 - y2 ; prox ----
        float sumsq = 0.f;
        #pragma unroll
        for (int q = 0; q < 16; q++) {
            int j = q * 32 + l;
            int o = s_cp4[j], e = s_cp4[j + 1];
            float g = 0.f;
            for (int p = o; p < e; p += 4) {
                unsigned w4 = *(const unsigned int*)&s_ci4[p];
                g += sy1[w4 & 255u] + sy1[(w4 >> 8) & 255u]
                   + sy1[(w4 >> 16) & 255u] + sy1[w4 >> 24];
            }
            g -= y2[q];
            float v = fmaf(-tau, g, xr[q]);
            float d = v + tau - Zr[q];     // + tau*W, W=1
            dq[q] = d;
            sumsq = fmaf(d, d, sumsq);
        }
        #pragma unroll
        for (int o = 16; o; o >>= 1) sumsq += __shfl_xor_sync(0xffffffffu, sumsq, o);
        float nrm = sqrtf(sumsq);
        float scale = fmaxf(1.f - tau / fmaxf(nrm, 1e-12f), 0.f);

        #pragma unroll
        for (int q = 0; q < 16; q++) {
            int j = q * 32 + l;
            float xn  = fmaf(scale, dq[q], Zr[q]);
            float xbv = 2.f * xn - xr[q];
            xr[q] = xn;
            xb[q] = xbv;
            sx[j] = xbv;
        }
        __syncwarp();
    }

    #pragma unroll
    for (int q = 0; q < 16; q++)
        out[(size_t)row * N_STRUCTS + q * 32 + l] = xr[q];
}

// ---------------- launch ----------------
extern "C" void kernel_launch(void* const* d_in, const int* in_sizes, int n_in,
                              void* d_out, int out_size) {
    const float* X  = (const float*)d_in[0];
    const float* W1 = (const float*)d_in[1];
    const float* b1 = (const float*)d_in[2];
    const float* W2 = (const float*)d_in[3];
    const float* b2 = (const float*)d_in[4];
    const float* W3 = (const float*)d_in[5];
    const float* b3 = (const float*)d_in[6];
    const float* S  = (const float*)d_in[7];
    float* out = (float*)d_out;

    float *A1, *A2, *Z;
    cudaGetSymbolAddress((void**)&A1, g_A1);
    cudaGetSymbolAddress((void**)&A2, g_A2);
    cudaGetSymbolAddress((void**)&Z,  g_Z);

    prep_kernel<<<1, 512>>>(S);
    power_kernel<<<1, 512>>>();

    gemm_bias_relu<64, 64, 16, 4, 4><<<dim3(HID / 64, BATCH / 64), 256>>>(
        X, W1, b1, A1, BATCH, HID, N_COMBOS);
    gemm_bias_relu<64, 64, 16, 4, 4><<<dim3(HID / 64, BATCH / 64), 256>>>(
        A1, W2, b2, A2, BATCH, HID, HID);
    gemm_bias_relu<64, 64, 16, 4, 4><<<dim3(N_STRUCTS / 64, BATCH / 64), 256>>>(
        A2, W3, b3, Z, BATCH, N_STRUCTS, HID);

    pdhg_warp_kernel<<<BATCH / ROWS_PER_BLK, 256>>>(Z, X, out);
}